// round 8
// baseline (speedup 1.0000x reference)
#include <cuda_runtime.h>

// Problem shape (fixed by the dataset)
#define BATCH 8
#define CHANS 3
#define IMG_H 720
#define IMG_W 1280
#define EPS_F 1e-6f
// log2(1.414) in double precision
#define LOG2_WARP_BASE 0.49978212546913446f

#define NC 42                 // iterations per lane; lane stride 42 >= tap reach
#define STG 1312              // skewed staging array size (max used index 1309)

__device__ __forceinline__ float fast_exp2(float x) {
    float r; asm("ex2.approx.f32 %0, %1;" : "=f"(r) : "f"(x)); return r;
}

// One row per block, 96 threads = 3 role-warps.
//   warp 0 -> ba[x] = {splat(im0*wm), splat(im1*wm)}   (float2 RMW)
//   warp 1 -> bb[x] = {splat(im2*wm), splat(wm)}       (float2 RMW)
//   warp 2 -> bo[x] = splat(1)                          (scalar RMW)
// Lane l owns columns 42*l + c; tap windows (col-40, col+1] of distinct lanes
// are disjoint (stride 42 >= reach 42) and roles touch disjoint arrays, so all
// bin updates are plain LDS+FFMA+STS — no atomics. Static smem 46.5 KB < 48 KB.
__global__ __launch_bounds__(96)
void warp_row_kernel(const float* __restrict__ im,
                     const float* __restrict__ disp,
                     float* __restrict__ out_res,
                     float* __restrict__ out_occ) {
    __shared__ float2 ba[IMG_W];
    __shared__ float2 bb[IMG_W];
    __shared__ float  bo[IMG_W];
    __shared__ float  sd[STG];     // staged disp, skewed
    __shared__ float2 sab[STG];    // staged {im0, im1}, skewed
    __shared__ float  s2[STG];     // staged im2, skewed

    const int tid = threadIdx.x;   // 0..95
    const int warp = tid >> 5;     // role 0,1,2
    const int lane = tid & 31;

    const int row = blockIdx.x;    // b*H + y
    const int b = row / IMG_H;
    const int y = row - b * IMG_H;

    const float* drow = disp + (size_t)row * IMG_W;
    const float* g0 = im + (((size_t)b * CHANS + 0) * IMG_H + y) * IMG_W;
    const float* g1 = im + (((size_t)b * CHANS + 1) * IMG_H + y) * IMG_W;
    const float* g2 = im + (((size_t)b * CHANS + 2) * IMG_H + y) * IMG_W;

    // Zero bins + stage the row into skewed smem (p = i + i/42 makes the
    // stride-42 compute-phase accesses bank-conflict-free).
    for (int i = tid; i < IMG_W; i += 96) {
        ba[i] = make_float2(0.0f, 0.0f);
        bb[i] = make_float2(0.0f, 0.0f);
        bo[i] = 0.0f;
        int p = i + i / 42;
        sd[p] = drow[i];
        sab[p] = make_float2(g0[i], g1[i]);
        s2[p] = g2[i];
    }
    __syncthreads();

    // Main splat loop: lane l handles col = 42*l + c.
    #pragma unroll 2
    for (int c = 0; c < NC; c++) {
        int col = 42 * lane + c;
        if (col < IMG_W) {
            int p = 43 * lane + c;                 // skewed staging index
            float d = sd[p];
            float x = (float)col - d;
            float x0f = floorf(x);
            int xi = (int)x0f;
            int xj = xi + 1;
            float wx1 = x - x0f;
            float wx0 = 1.0f - wx1;
            bool oki = (xi >= 0);                  // xi <= col < W always
            bool okj = (xj >= 0) && (xj < IMG_W);
            if (warp == 0) {
                float wm = fast_exp2(d * (float)LOG2_WARP_BASE);
                float2 s = sab[p];
                float v0 = s.x * wm;
                float v1 = s.y * wm;
                if (oki) { float2 t = ba[xi]; t.x += v0 * wx0; t.y += v1 * wx0; ba[xi] = t; }
                if (okj) { float2 t = ba[xj]; t.x += v0 * wx1; t.y += v1 * wx1; ba[xj] = t; }
            } else if (warp == 1) {
                float wm = fast_exp2(d * (float)LOG2_WARP_BASE);
                float v2 = s2[p] * wm;
                if (oki) { float2 t = bb[xi]; t.x += v2 * wx0; t.y += wm * wx0; bb[xi] = t; }
                if (okj) { float2 t = bb[xj]; t.x += v2 * wx1; t.y += wm * wx1; bb[xj] = t; }
            } else {
                if (oki) bo[xi] += wx0;
                if (okj) bo[xj] += wx1;
            }
        }
    }
    __syncthreads();

    // Epilogue: normalize + occlusion. 96-thread strided loop; each warp's 32
    // consecutive columns give coalesced 128B global stores.
    float* r0 = out_res + (((size_t)b * CHANS + 0) * IMG_H + y) * IMG_W;
    float* r1 = out_res + (((size_t)b * CHANS + 1) * IMG_H + y) * IMG_W;
    float* r2 = out_res + (((size_t)b * CHANS + 2) * IMG_H + y) * IMG_W;
    float* oc = out_occ + (size_t)row * IMG_W;

    for (int i = tid; i < IMG_W; i += 96) {
        float2 a = ba[i];
        float2 bq = bb[i];
        float o = bo[i];
        float inv = 1.0f / fmaxf(bq.y, EPS_F);
        r0[i] = a.x * inv;
        r1[i] = a.y * inv;
        r2[i] = bq.x * inv;
        oc[i] = 1.0f - __saturatef(o);
    }
}

extern "C" void kernel_launch(void* const* d_in, const int* in_sizes, int n_in,
                              void* d_out, int out_size) {
    const float* im = (const float*)d_in[0];
    const float* disp = (const float*)d_in[1];
    float* out_res = (float*)d_out;
    float* out_occ = (float*)d_out + (size_t)BATCH * CHANS * IMG_H * IMG_W;

    warp_row_kernel<<<BATCH * IMG_H, 96>>>(im, disp, out_res, out_occ);
}

// round 9
// speedup vs baseline: 1.4180x; 1.4180x over previous
#include <cuda_runtime.h>

// Problem shape (fixed by the dataset)
#define BATCH 8
#define CHANS 3
#define IMG_H 720
#define IMG_W 1280
#define EPS_F 1e-6f
// log2(1.414) in double precision
#define LOG2_WARP_BASE 0.49978212546913446f

// Global scratch: per-pixel float4 accumulator {acc0, acc1, acc2, mask}.
// Each row-block owns its 1280*16B slice exclusively (taps never leave the row),
// so it is zeroed, red-accumulated, read back, and discarded entirely within one
// block's lifetime -> stays L2-resident.
__device__ float4 g_acc[(size_t)BATCH * IMG_H * IMG_W];

__device__ __forceinline__ float fast_exp2(float x) {
    float r; asm("ex2.approx.f32 %0, %1;" : "=f"(r) : "f"(x)); return r;
}

// Vector reduction (no return) into global memory: one op carries 4 floats.
__device__ __forceinline__ void red_add_v4(float4* p, float a, float b, float c, float d) {
    asm volatile("red.global.add.v4.f32 [%0], {%1, %2, %3, %4};"
                 :: "l"(p), "f"(a), "f"(b), "f"(c), "f"(d) : "memory");
}

// Discard a 128B L2 line (scratch is dead after readback; avoids DRAM writeback).
__device__ __forceinline__ void l2_discard(const void* p) {
    asm volatile("discard.global.L2 [%0], 128;" :: "l"(p) : "memory");
}

// One row per block (256 threads). Lane l owns columns 41*l + c (c = 0..40):
// per-instruction lane tap windows are disjoint -> no same-address replays.
// Channels+mask splat via red.global.v4 (L2 atomic units); ones splat in smem.
__global__ __launch_bounds__(256)
void warp_row_kernel(const float* __restrict__ im,
                     const float* __restrict__ disp,
                     float* __restrict__ out_res,
                     float* __restrict__ out_occ) {
    __shared__ float4 st[IMG_W];     // staged {d, im0, im1, im2}
    __shared__ float  sones[IMG_W];  // ones-splat bins

    const int tid = threadIdx.x;
    const int w = tid >> 5;
    const int lane = tid & 31;

    const int row = blockIdx.x;      // b*H + y
    const int b = row / IMG_H;
    const int y = row - b * IMG_H;

    float4* arow = g_acc + (size_t)row * IMG_W;

    const float* drow = disp + (size_t)row * IMG_W;
    const float* g0 = im + (((size_t)b * CHANS + 0) * IMG_H + y) * IMG_W;
    const float* g1 = im + (((size_t)b * CHANS + 1) * IMG_H + y) * IMG_W;
    const float* g2 = im + (((size_t)b * CHANS + 2) * IMG_H + y) * IMG_W;

    // Zero global scratch row + smem ones bins; stage inputs into smem.
    {
        const float4 z4 = make_float4(0.f, 0.f, 0.f, 0.f);
        #pragma unroll
        for (int k = 0; k < IMG_W / 256; k++) {
            int i = tid + 256 * k;
            st[i] = make_float4(drow[i], g0[i], g1[i], g2[i]);
            sones[i] = 0.0f;
            arow[i] = z4;
        }
    }
    __syncthreads();

    // Splat. Warp w handles c = w, w+8, ... (c in [0,41)); lane l -> col 41*l+c.
    for (int c = w; c < 41; c += 8) {
        int col = 41 * lane + c;
        if (col < IMG_W) {
            float4 s = st[col];
            float d = s.x;
            float wm = fast_exp2(d * (float)LOG2_WARP_BASE);
            float x = (float)col - d;
            float x0f = floorf(x);
            int xi = (int)x0f;
            int xj = xi + 1;
            float wx1 = x - x0f;
            float wx0 = 1.0f - wx1;
            float v0 = s.y * wm;
            float v1 = s.z * wm;
            float v2 = s.w * wm;
            if (xi >= 0) {                      // xi <= col < W always
                red_add_v4(arow + xi, v0 * wx0, v1 * wx0, v2 * wx0, wm * wx0);
                atomicAdd(&sones[xi], wx0);
            }
            if (xj >= 0 && xj < IMG_W) {
                red_add_v4(arow + xj, v0 * wx1, v1 * wx1, v2 * wx1, wm * wx1);
                atomicAdd(&sones[xj], wx1);
            }
        }
    }
    __threadfence();      // make this thread's reds visible before readback
    __syncthreads();

    // Epilogue: read back (L2-hit), normalize, occlusion.
    float* r0 = out_res + (((size_t)b * CHANS + 0) * IMG_H + y) * IMG_W;
    float* r1 = out_res + (((size_t)b * CHANS + 1) * IMG_H + y) * IMG_W;
    float* r2 = out_res + (((size_t)b * CHANS + 2) * IMG_H + y) * IMG_W;
    float* oc = out_occ + (size_t)row * IMG_W;

    #pragma unroll
    for (int k = 0; k < IMG_W / 256; k++) {
        int i = tid + 256 * k;
        float4 q = arow[i];
        float inv = 1.0f / fmaxf(q.w, EPS_F);
        r0[i] = q.x * inv;
        r1[i] = q.y * inv;
        r2[i] = q.z * inv;
        oc[i] = 1.0f - __saturatef(sones[i]);
    }
    __syncthreads();      // all readbacks of arow complete

    // Discard the dead scratch lines (160 x 128B per row) to avoid DRAM writeback.
    if (tid < (IMG_W * 16) / 128) {
        l2_discard((const char*)arow + tid * 128);
    }
}

extern "C" void kernel_launch(void* const* d_in, const int* in_sizes, int n_in,
                              void* d_out, int out_size) {
    const float* im = (const float*)d_in[0];
    const float* disp = (const float*)d_in[1];
    float* out_res = (float*)d_out;
    float* out_occ = (float*)d_out + (size_t)BATCH * CHANS * IMG_H * IMG_W;

    warp_row_kernel<<<BATCH * IMG_H, 256>>>(im, disp, out_res, out_occ);
}

// round 10
// speedup vs baseline: 1.5995x; 1.1280x over previous
#include <cuda_runtime.h>

// Problem shape (fixed by the dataset)
#define BATCH 8
#define CHANS 3
#define IMG_H 720
#define IMG_W 1280
#define EPS_F 1e-6f
// log2(1.414) in double precision
#define LOG2_WARP_BASE 0.49978212546913446f

// Global scratch: per-pixel float4 accumulator {acc0, acc1, acc2, mask}.
// Each row-block owns its 1280*16B slice exclusively (taps never leave the row):
// zeroed, red-accumulated, read back, and discarded within one block lifetime
// -> stays L2-resident (active set ~15 MB << 126 MB L2).
__device__ float4 g_acc[(size_t)BATCH * IMG_H * IMG_W];

__device__ __forceinline__ float fast_exp2(float x) {
    float r; asm("ex2.approx.f32 %0, %1;" : "=f"(r) : "f"(x)); return r;
}

// Vector reduction (no return) into global memory: one op carries 4 floats.
// Same-address collisions between lanes are handled by the L2 atomic units at
// full rate, so lanes may target ADJACENT bins (few cache lines per instr).
__device__ __forceinline__ void red_add_v4(float4* p, float a, float b, float c, float d) {
    asm volatile("red.global.add.v4.f32 [%0], {%1, %2, %3, %4};"
                 :: "l"(p), "f"(a), "f"(b), "f"(c), "f"(d) : "memory");
}

// Discard a 128B L2 line (scratch is dead after readback; avoids DRAM writeback).
__device__ __forceinline__ void l2_discard(const void* p) {
    asm volatile("discard.global.L2 [%0], 128;" :: "l"(p) : "memory");
}

// One row per block (256 threads). Lanes of each warp-instruction process 32
// CONSECUTIVE columns, so the red.v4 targets of a warp fall in a 72-bin window
// (~10 cache lines/instr instead of 32 with a spread mapping) — the L1tex
// wavefront and L2 sector cost per scatter drops ~3x.
__global__ __launch_bounds__(256)
void warp_row_kernel(const float* __restrict__ im,
                     const float* __restrict__ disp,
                     float* __restrict__ out_res,
                     float* __restrict__ out_occ) {
    __shared__ __align__(16) float sd[IMG_W];     // staged disp
    __shared__ __align__(16) float s0[IMG_W];     // staged im0
    __shared__ __align__(16) float s1[IMG_W];     // staged im1
    __shared__ __align__(16) float s2[IMG_W];     // staged im2
    __shared__ __align__(16) float sones[IMG_W];  // ones-splat bins

    const int tid = threadIdx.x;
    const int w = tid >> 5;
    const int lane = tid & 31;

    const int row = blockIdx.x;      // b*H + y
    const int b = row / IMG_H;
    const int y = row - b * IMG_H;

    float4* arow = g_acc + (size_t)row * IMG_W;

    const float4* d4 = (const float4*)(disp + (size_t)row * IMG_W);
    const float4* a4 = (const float4*)(im + (((size_t)b * CHANS + 0) * IMG_H + y) * IMG_W);
    const float4* b4 = (const float4*)(im + (((size_t)b * CHANS + 1) * IMG_H + y) * IMG_W);
    const float4* c4 = (const float4*)(im + (((size_t)b * CHANS + 2) * IMG_H + y) * IMG_W);

    // Stage inputs (float4 loads) + zero smem ones bins + zero global scratch.
    {
        const float4 z4 = make_float4(0.f, 0.f, 0.f, 0.f);
        #pragma unroll
        for (int k = 0; k < (IMG_W / 4) / 256 + 1; k++) {     // 320 float4s
            int q = tid + 256 * k;
            if (q < IMG_W / 4) {
                ((float4*)sd)[q] = d4[q];
                ((float4*)s0)[q] = a4[q];
                ((float4*)s1)[q] = b4[q];
                ((float4*)s2)[q] = c4[q];
                ((float4*)sones)[q] = z4;
            }
        }
        #pragma unroll
        for (int k = 0; k < IMG_W / 256; k++)                 // 1280 float4 bins
            arow[tid + 256 * k] = z4;
    }
    __syncthreads();

    // Splat. Warp w owns columns [160w, 160w+160); iteration k covers the
    // consecutive 32-column slab 160w + 32k + lane. 8*5*32 = 1280 exactly.
    #pragma unroll
    for (int k = 0; k < 5; k++) {
        int col = 160 * w + 32 * k + lane;
        float d = sd[col];
        float wm = fast_exp2(d * (float)LOG2_WARP_BASE);
        float x = (float)col - d;
        float x0f = floorf(x);
        int xi = (int)x0f;
        int xj = xi + 1;
        float wx1 = x - x0f;
        float wx0 = 1.0f - wx1;
        float v0 = s0[col] * wm;
        float v1 = s1[col] * wm;
        float v2 = s2[col] * wm;
        if (xi >= 0) {                       // xi <= col < W always
            red_add_v4(arow + xi, v0 * wx0, v1 * wx0, v2 * wx0, wm * wx0);
            atomicAdd(&sones[xi], wx0);
        }
        if (xj >= 0 && xj < IMG_W) {
            red_add_v4(arow + xj, v0 * wx1, v1 * wx1, v2 * wx1, wm * wx1);
            atomicAdd(&sones[xj], wx1);
        }
    }
    __threadfence();      // make this thread's reds visible before readback
    __syncthreads();

    // Epilogue: read back (L2-hit, coalesced LDG.128), normalize, occlusion.
    float* r0 = out_res + (((size_t)b * CHANS + 0) * IMG_H + y) * IMG_W;
    float* r1 = out_res + (((size_t)b * CHANS + 1) * IMG_H + y) * IMG_W;
    float* r2 = out_res + (((size_t)b * CHANS + 2) * IMG_H + y) * IMG_W;
    float* oc = out_occ + (size_t)row * IMG_W;

    #pragma unroll
    for (int k = 0; k < IMG_W / 256; k++) {
        int i = tid + 256 * k;
        float4 q = arow[i];
        float inv = 1.0f / fmaxf(q.w, EPS_F);
        r0[i] = q.x * inv;
        r1[i] = q.y * inv;
        r2[i] = q.z * inv;
        oc[i] = 1.0f - __saturatef(sones[i]);
    }
    __syncthreads();      // all readbacks of arow complete

    // Discard the dead scratch lines (160 x 128B per row) to avoid DRAM writeback.
    if (tid < (IMG_W * 16) / 128) {
        l2_discard((const char*)arow + tid * 128);
    }
}

extern "C" void kernel_launch(void* const* d_in, const int* in_sizes, int n_in,
                              void* d_out, int out_size) {
    const float* im = (const float*)d_in[0];
    const float* disp = (const float*)d_in[1];
    float* out_res = (float*)d_out;
    float* out_occ = (float*)d_out + (size_t)BATCH * CHANS * IMG_H * IMG_W;

    warp_row_kernel<<<BATCH * IMG_H, 256>>>(im, disp, out_res, out_occ);
}